// round 14
// baseline (speedup 1.0000x reference)
#include <cuda_runtime.h>
#include <cuda_bf16.h>
#include <cstdint>

// ExpandHarmonics. Output (float32): [hkl 3M | dHKL M | wav M | meta DM*M].
// R14: 512-thread count/pack blocks (2048 rows each) to halve per-block fixed
//      costs; KB=4 fused copy + vectorized scalar blocks unchanged (proven).

#define MAXN   (1 << 20)
#define BLK    512
#define ROWS_PT 4
#define ROWS_PB (BLK * ROWS_PT)                  // 2048 rows per block
#define MAXB   ((MAXN + ROWS_PB - 1) / ROWS_PB)
#define MAXM   (1 << 23)

__device__ int           g_rowoff[MAXN];
__device__ unsigned char g_cnt[MAXN];
__device__ int           g_blocksum[MAXB];
__device__ int           g_pack[MAXM];       // (src_idx << 8) | harmonic_n
__device__ unsigned int  g_hkl0[MAXN];       // h0 | k0<<8 | l0<<16
__device__ float         g_d0[MAXN];         // dHKL * g
__device__ float         g_w0[MAXN];         // wavelength * g

__device__ __forceinline__ int bgcd(int a, int b) {
    int s = __ffs(a | b) - 1;
    a >>= (__ffs(a) - 1);
    do {
        b >>= (__ffs(b) - 1);
        if (a > b) { int t = a; a = b; b = t; }
        b -= a;
    } while (b);
    return a << s;
}

// ---- Pass 1: count + precompute, 4 rows/thread, 512-thread blocks ----
__global__ __launch_bounds__(BLK)
void k_count(const int* __restrict__ hkl, const float* __restrict__ dHKL,
             const float* __restrict__ wav, const float* __restrict__ dmin, int N) {
    const int t = threadIdx.x;
    const int wid = t >> 5, lane = t & 31;
    const int i0 = blockIdx.x * ROWS_PB + t * ROWS_PT;
    const float dm = __ldg(dmin);

    int hh[4], kk[4], ll[4];
    float dv[4], wv[4];
    bool full = (i0 + ROWS_PT <= N);
    if (full) {
        const int4* hp = (const int4*)(hkl + 3 * i0);
        int4 a = hp[0], b = hp[1], c = hp[2];
        hh[0]=a.x; kk[0]=a.y; ll[0]=a.z;
        hh[1]=a.w; kk[1]=b.x; ll[1]=b.y;
        hh[2]=b.z; kk[2]=b.w; ll[2]=c.x;
        hh[3]=c.y; kk[3]=c.z; ll[3]=c.w;
        float4 d4 = *(const float4*)(dHKL + i0);
        float4 w4 = *(const float4*)(wav + i0);
        dv[0]=d4.x; dv[1]=d4.y; dv[2]=d4.z; dv[3]=d4.w;
        wv[0]=w4.x; wv[1]=w4.y; wv[2]=w4.z; wv[3]=w4.w;
    } else {
        #pragma unroll
        for (int j = 0; j < 4; j++) {
            int i = i0 + j;
            if (i < N) {
                hh[j]=hkl[3*i]; kk[j]=hkl[3*i+1]; ll[j]=hkl[3*i+2];
                dv[j]=dHKL[i]; wv[j]=wav[i];
            } else { hh[j]=1; kk[j]=1; ll[j]=1; dv[j]=0.f; wv[j]=0.f; }
        }
    }

    int cnt[4];
    unsigned hk0[4];
    float d0v[4], w0v[4];
    #pragma unroll
    for (int j = 0; j < 4; j++) {
        int g = bgcd(bgcd(hh[j], kk[j]), ll[j]);
        float fg = (float)g;
        float rg = 1.0f / fg;
        float d0 = dv[j] * fg;
        int c = (int)floorf(d0 / dm);
        cnt[j] = (i0 + j < N) ? c : 0;
        unsigned h0 = (unsigned)__float2int_rn((float)hh[j] * rg);
        unsigned k0 = (unsigned)__float2int_rn((float)kk[j] * rg);
        unsigned l0 = (unsigned)__float2int_rn((float)ll[j] * rg);
        hk0[j] = h0 | (k0 << 8) | (l0 << 16);
        d0v[j] = d0;
        w0v[j] = wv[j] * fg;
    }
    int tsum = cnt[0] + cnt[1] + cnt[2] + cnt[3];

    int incl = tsum;
    #pragma unroll
    for (int o = 1; o < 32; o <<= 1) {
        int v = __shfl_up_sync(0xffffffffu, incl, o);
        if (lane >= o) incl += v;
    }
    __shared__ int s_wbase[16];
    if (lane == 31) s_wbase[wid] = incl;
    __syncthreads();
    if (wid == 0) {
        int v = (lane < 16) ? s_wbase[lane] : 0;
        int sc = v;
        #pragma unroll
        for (int o = 1; o < 16; o <<= 1) {
            int u = __shfl_up_sync(0xffffffffu, sc, o);
            if (lane >= o) sc += u;
        }
        if (lane < 16) s_wbase[lane] = sc - v;
        if (lane == 15) g_blocksum[blockIdx.x] = sc;
    }
    __syncthreads();

    int texc = s_wbase[wid] + (incl - tsum);
    int ro[4];
    ro[0] = texc;
    ro[1] = ro[0] + cnt[0];
    ro[2] = ro[1] + cnt[1];
    ro[3] = ro[2] + cnt[2];

    if (full) {
        *(uint4*)(g_hkl0 + i0)  = make_uint4(hk0[0], hk0[1], hk0[2], hk0[3]);
        *(float4*)(g_d0 + i0)   = make_float4(d0v[0], d0v[1], d0v[2], d0v[3]);
        *(float4*)(g_w0 + i0)   = make_float4(w0v[0], w0v[1], w0v[2], w0v[3]);
        *(int4*)(g_rowoff + i0) = make_int4(ro[0], ro[1], ro[2], ro[3]);
        *(uchar4*)(g_cnt + i0)  = make_uchar4((unsigned char)cnt[0], (unsigned char)cnt[1],
                                              (unsigned char)cnt[2], (unsigned char)cnt[3]);
    } else {
        #pragma unroll
        for (int j = 0; j < 4; j++) {
            int i = i0 + j;
            if (i < N) {
                g_hkl0[i] = hk0[j]; g_d0[i] = d0v[j]; g_w0[i] = w0v[j];
                g_rowoff[i] = ro[j]; g_cnt[i] = (unsigned char)cnt[j];
            }
        }
    }
}

// ---- Pass 2: pack; one 512-thread block per count-block ----
__global__ __launch_bounds__(BLK)
void k_pack(int N) {
    const int b = blockIdx.x;
    const int t = threadIdx.x;
    const int wid = t >> 5, lane = t & 31;

    // sum g_blocksum[0..b): b <= 511, so <= 1 load per thread
    int partial = (t < b) ? g_blocksum[t] : 0;
    #pragma unroll
    for (int o = 16; o > 0; o >>= 1)
        partial += __shfl_down_sync(0xffffffffu, partial, o);
    __shared__ int s_w[16];
    __shared__ int s_base;
    if (lane == 0) s_w[wid] = partial;
    __syncthreads();
    if (t == 0) {
        int s = 0;
        #pragma unroll
        for (int w = 0; w < 16; w++) s += s_w[w];
        s_base = s;
    }
    __syncthreads();

    int i0 = b * ROWS_PB + t * ROWS_PT;
    if (i0 >= N) return;
    if (i0 + ROWS_PT <= N) {
        int4 ro = *(const int4*)(g_rowoff + i0);
        uchar4 c4 = *(const uchar4*)(g_cnt + i0);
        int roa[4] = {ro.x, ro.y, ro.z, ro.w};
        int ca[4]  = {c4.x, c4.y, c4.z, c4.w};
        #pragma unroll
        for (int j = 0; j < 4; j++) {
            int off = s_base + roa[j];
            int tag = (i0 + j) << 8;
            for (int n = 1; n <= ca[j]; n++)
                g_pack[off + n - 1] = tag | n;
        }
    } else {
        for (int j = 0; j < 4; j++) {
            int i = i0 + j;
            if (i >= N) break;
            int off = s_base + g_rowoff[i];
            int cnt = g_cnt[i];
            int tag = i << 8;
            for (int n = 1; n <= cnt; n++)
                g_pack[off + n - 1] = tag | n;
        }
    }
}

// ---- Pass 3 (fused): meta copy (KB=4) + vectorized scalar outputs ----
template<int LEAD>
__global__ __launch_bounds__(256)
void k_fused(const float* __restrict__ meta, float* __restrict__ out,
             int M, int DMs, unsigned T, unsigned NV, int metaBlocks) {
    if ((int)blockIdx.x >= metaBlocks) {
        int m0 = (blockIdx.x - metaBlocks) * 1024 + threadIdx.x * 4;
        if (m0 + 4 <= M) {
            int4 p4 = *(const int4*)(g_pack + m0);
            int pk[4] = {p4.x, p4.y, p4.z, p4.w};
            float hv[12];
            #pragma unroll
            for (int j = 0; j < 4; j++) {
                int idx = pk[j] >> 8;
                int n   = pk[j] & 255;
                unsigned hp = g_hkl0[idx];
                float fn = (float)n;
                hv[3*j+0] = (float)((int)(hp & 255u) * n);
                hv[3*j+1] = (float)((int)((hp >> 8) & 255u) * n);
                hv[3*j+2] = (float)((int)(hp >> 16) * n);
                out[3 * M + m0 + j] = g_d0[idx] / fn;
                out[4 * M + m0 + j] = g_w0[idx] / fn;
            }
            float4* hdst = (float4*)(out + 3 * (size_t)m0);
            hdst[0] = make_float4(hv[0], hv[1], hv[2],  hv[3]);
            hdst[1] = make_float4(hv[4], hv[5], hv[6],  hv[7]);
            hdst[2] = make_float4(hv[8], hv[9], hv[10], hv[11]);
        } else {
            for (int j = 0; j < 4; j++) {
                int m = m0 + j;
                if (m >= M) break;
                int pack = g_pack[m];
                int idx = pack >> 8;
                int n   = pack & 255;
                unsigned hp = g_hkl0[idx];
                float fn = (float)n;
                out[3 * m + 0] = (float)((int)(hp & 255u) * n);
                out[3 * m + 1] = (float)((int)((hp >> 8) & 255u) * n);
                out[3 * m + 2] = (float)((int)(hp >> 16) * n);
                out[3 * M + m] = g_d0[idx] / fn;
                out[4 * M + m] = g_w0[idx] / fn;
            }
        }
        return;
    }

    const unsigned DMm = (1u << DMs) - 1u;
    const size_t gbase = (size_t)5 * M;
    const unsigned GMAX = T >> 2;

    unsigned w    = blockIdx.x * 8u + (threadIdx.x >> 5);
    int      lane = threadIdx.x & 31;
    unsigned fb   = w * 128u + (unsigned)lane;

    float4 v[5];
    #pragma unroll
    for (int k2 = 0; k2 < 4; k2++) {
        unsigned g = fb + 32u * (unsigned)k2;
        v[k2] = make_float4(0.f, 0.f, 0.f, 0.f);
        if (g < GMAX) {
            unsigned p = 4u * g;
            unsigned idx = ((unsigned)__ldg(&g_pack[p >> DMs])) >> 8;
            v[k2] = *(const float4*)(meta + (size_t)((idx << DMs) + (p & DMm)));
        }
    }
    if (LEAD != 0) {
        v[4] = make_float4(0.f, 0.f, 0.f, 0.f);
        if (lane == 0) {
            unsigned g = w * 128u + 128u;
            if (g < GMAX) {
                unsigned p = 4u * g;
                unsigned idx = ((unsigned)__ldg(&g_pack[p >> DMs])) >> 8;
                v[4] = *(const float4*)(meta + (size_t)((idx << DMs) + (p & DMm)));
            }
        }
    }

    float* dstf = out + gbase + (size_t)LEAD;
    #pragma unroll
    for (int k2 = 0; k2 < 4; k2++) {
        float4 o;
        if (LEAD == 0) {
            o = v[k2];
        } else {
            float4 vnext = (k2 < 3) ? v[k2 + 1] : v[4];
            float nx = __shfl_sync(0xffffffffu, vnext.x, 0);
            float sx = __shfl_down_sync(0xffffffffu, v[k2].x, 1);
            float vnx = (lane == 31) ? nx : sx;
            float vny = 0.f, vnz = 0.f;
            if (LEAD >= 2) {
                float ny = __shfl_sync(0xffffffffu, vnext.y, 0);
                float sy = __shfl_down_sync(0xffffffffu, v[k2].y, 1);
                vny = (lane == 31) ? ny : sy;
            }
            if (LEAD == 3) {
                float nz = __shfl_sync(0xffffffffu, vnext.z, 0);
                float sz = __shfl_down_sync(0xffffffffu, v[k2].z, 1);
                vnz = (lane == 31) ? nz : sz;
            }
            if (LEAD == 1)      o = make_float4(v[k2].y, v[k2].z, v[k2].w, vnx);
            else if (LEAD == 2) o = make_float4(v[k2].z, v[k2].w, vnx, vny);
            else                o = make_float4(v[k2].w, vnx, vny, vnz);
        }
        unsigned f = fb + 32u * (unsigned)k2;
        if (f < NV)
            *(float4*)(dstf + 4 * (size_t)f) = o;
    }

    if (blockIdx.x == 0 && threadIdx.x < 32) {
        if (lane < LEAD) {
            unsigned idx = ((unsigned)g_pack[0]) >> 8;
            out[gbase + lane] = meta[(size_t)((idx << DMs) + lane)];
        }
        unsigned done = (unsigned)LEAD + 4u * NV;
        unsigned tail = T - done;
        if (lane >= 4 && lane < 4 + (int)tail) {
            unsigned p = done + (unsigned)(lane - 4);
            unsigned idx = ((unsigned)g_pack[p >> DMs]) >> 8;
            out[gbase + p] = meta[(size_t)((idx << DMs) + (p & DMm))];
        }
    }
}

// ---- Fallbacks (DM not power of two) ----
__global__ __launch_bounds__(256)
void k_scalar_fb(float* __restrict__ out, int M) {
    int m = blockIdx.x * 256 + threadIdx.x;
    if (m >= M) return;
    int pack = g_pack[m];
    int idx = pack >> 8;
    int n   = pack & 255;
    unsigned hp = g_hkl0[idx];
    float fn = (float)n;
    out[3 * m + 0] = (float)((int)(hp & 255u) * n);
    out[3 * m + 1] = (float)((int)((hp >> 8) & 255u) * n);
    out[3 * m + 2] = (float)((int)(hp >> 16) * n);
    out[3 * M + m] = g_d0[idx] / fn;
    out[4 * M + m] = g_w0[idx] / fn;
}

__global__ __launch_bounds__(256)
void k_meta_fb(const float* __restrict__ meta, float* __restrict__ out, int M, int DM) {
    int gw   = (blockIdx.x * 256 + threadIdx.x) >> 5;
    int lane = threadIdx.x & 31;
    int r = lane >> 3;
    int c = lane & 7;
    int m = gw * 4 + r;
    if (m >= M) return;
    int idx = g_pack[m] >> 8;
    const float* src = meta + (size_t)idx * DM;
    float*       dst = out + (size_t)5 * M + (size_t)m * DM;
    for (int e = c; e < DM; e += 8)
        dst[e] = src[e];
}

extern "C" void kernel_launch(void* const* d_in, const int* in_sizes, int n_in,
                              void* d_out, int out_size) {
    const int*   hkl  = (const int*)  d_in[0];
    const float* dHKL = (const float*)d_in[1];
    const float* wav  = (const float*)d_in[2];
    const float* meta = (const float*)d_in[3];
    const float* dmin = (const float*)d_in[4];

    int N  = in_sizes[1];
    int DM = in_sizes[3] / N;
    int M  = out_size / (5 + DM);

    int B = (N + ROWS_PB - 1) / ROWS_PB;     // <= 512 blocks for N <= 1M

    k_count<<<B, BLK>>>(hkl, dHKL, wav, dmin, N);
    k_pack<<<B, BLK>>>(N);

    bool pow2 = (DM >= 4) && ((DM & (DM - 1)) == 0);
    if (pow2) {
        int DMs = 0; while ((1 << DMs) < DM) DMs++;
        unsigned T = (unsigned)((size_t)M << DMs);
        int lead = (int)((4u - ((5u * (unsigned)M) & 3u)) & 3u);
        unsigned NV = (T - (unsigned)lead) >> 2;
        unsigned metaWarps = (NV + 127u) / 128u;
        int metaBlocks = (int)((metaWarps + 7u) / 8u);
        int scalarBlocks = (M + 1023) / 1024;
        int grid = metaBlocks + scalarBlocks;
        switch (lead) {
            case 0: k_fused<0><<<grid, 256>>>(meta, (float*)d_out, M, DMs, T, NV, metaBlocks); break;
            case 1: k_fused<1><<<grid, 256>>>(meta, (float*)d_out, M, DMs, T, NV, metaBlocks); break;
            case 2: k_fused<2><<<grid, 256>>>(meta, (float*)d_out, M, DMs, T, NV, metaBlocks); break;
            default: k_fused<3><<<grid, 256>>>(meta, (float*)d_out, M, DMs, T, NV, metaBlocks); break;
        }
    } else {
        k_scalar_fb<<<(M + 255) / 256, 256>>>((float*)d_out, M);
        int rowsPerBlock = 8 * 4;
        k_meta_fb<<<(M + rowsPerBlock - 1) / rowsPerBlock, 256>>>(meta, (float*)d_out, M, DM);
    }
}

// round 15
// speedup vs baseline: 1.0786x; 1.0786x over previous
#include <cuda_runtime.h>
#include <cuda_bf16.h>
#include <cstdint>

// ExpandHarmonics. Output (float32): [hkl 3M | dHKL M | wav M | meta DM*M].
// R15: count/pack at 2 rows/thread (occupancy/ILP balance point);
//      k_fused exactly R13 (KB=4 copy + vectorized scalar blocks).

#define MAXN   (1 << 20)
#define BLK    256
#define ROWS_PT 2
#define ROWS_PB (BLK * ROWS_PT)                  // 512 rows per block
#define MAXB   ((MAXN + ROWS_PB - 1) / ROWS_PB)
#define MAXM   (1 << 23)

__device__ int           g_rowoff[MAXN];
__device__ unsigned char g_cnt[MAXN];
__device__ int           g_blocksum[MAXB];
__device__ int           g_pack[MAXM];       // (src_idx << 8) | harmonic_n
__device__ unsigned int  g_hkl0[MAXN];       // h0 | k0<<8 | l0<<16
__device__ float         g_d0[MAXN];         // dHKL * g
__device__ float         g_w0[MAXN];         // wavelength * g

__device__ __forceinline__ int bgcd(int a, int b) {
    int s = __ffs(a | b) - 1;
    a >>= (__ffs(a) - 1);
    do {
        b >>= (__ffs(b) - 1);
        if (a > b) { int t = a; a = b; b = t; }
        b -= a;
    } while (b);
    return a << s;
}

// ---- Pass 1: count + precompute, 2 rows/thread ----
__global__ __launch_bounds__(BLK)
void k_count(const int* __restrict__ hkl, const float* __restrict__ dHKL,
             const float* __restrict__ wav, const float* __restrict__ dmin, int N) {
    const int t = threadIdx.x;
    const int wid = t >> 5, lane = t & 31;
    const int i0 = blockIdx.x * ROWS_PB + t * ROWS_PT;
    const float dm = __ldg(dmin);

    int hh[2], kk[2], ll[2];
    float dv[2], wv[2];
    bool full = (i0 + ROWS_PT <= N);
    if (full) {
        const int2* hp = (const int2*)(hkl + 3 * i0);    // 3*i0 even -> 8B aligned
        int2 a = hp[0], b = hp[1], c = hp[2];
        hh[0]=a.x; kk[0]=a.y; ll[0]=b.x;
        hh[1]=b.y; kk[1]=c.x; ll[1]=c.y;
        float2 d2 = *(const float2*)(dHKL + i0);
        float2 w2 = *(const float2*)(wav + i0);
        dv[0]=d2.x; dv[1]=d2.y;
        wv[0]=w2.x; wv[1]=w2.y;
    } else {
        #pragma unroll
        for (int j = 0; j < 2; j++) {
            int i = i0 + j;
            if (i < N) {
                hh[j]=hkl[3*i]; kk[j]=hkl[3*i+1]; ll[j]=hkl[3*i+2];
                dv[j]=dHKL[i]; wv[j]=wav[i];
            } else { hh[j]=1; kk[j]=1; ll[j]=1; dv[j]=0.f; wv[j]=0.f; }
        }
    }

    int cnt[2];
    unsigned hk0[2];
    float d0v[2], w0v[2];
    #pragma unroll
    for (int j = 0; j < 2; j++) {
        int g = bgcd(bgcd(hh[j], kk[j]), ll[j]);
        float fg = (float)g;
        float rg = 1.0f / fg;
        float d0 = dv[j] * fg;
        int c = (int)floorf(d0 / dm);
        cnt[j] = (i0 + j < N) ? c : 0;
        unsigned h0 = (unsigned)__float2int_rn((float)hh[j] * rg);
        unsigned k0 = (unsigned)__float2int_rn((float)kk[j] * rg);
        unsigned l0 = (unsigned)__float2int_rn((float)ll[j] * rg);
        hk0[j] = h0 | (k0 << 8) | (l0 << 16);
        d0v[j] = d0;
        w0v[j] = wv[j] * fg;
    }
    int tsum = cnt[0] + cnt[1];

    int incl = tsum;
    #pragma unroll
    for (int o = 1; o < 32; o <<= 1) {
        int v = __shfl_up_sync(0xffffffffu, incl, o);
        if (lane >= o) incl += v;
    }
    __shared__ int s_wbase[8];
    if (lane == 31) s_wbase[wid] = incl;
    __syncthreads();
    if (wid == 0) {
        int v = (lane < 8) ? s_wbase[lane] : 0;
        int sc = v;
        #pragma unroll
        for (int o = 1; o < 8; o <<= 1) {
            int u = __shfl_up_sync(0xffffffffu, sc, o);
            if (lane >= o) sc += u;
        }
        if (lane < 8) s_wbase[lane] = sc - v;
        if (lane == 7) g_blocksum[blockIdx.x] = sc;
    }
    __syncthreads();

    int texc = s_wbase[wid] + (incl - tsum);
    int ro0 = texc;
    int ro1 = ro0 + cnt[0];

    if (full) {
        *(uint2*)(g_hkl0 + i0)   = make_uint2(hk0[0], hk0[1]);
        *(float2*)(g_d0 + i0)    = make_float2(d0v[0], d0v[1]);
        *(float2*)(g_w0 + i0)    = make_float2(w0v[0], w0v[1]);
        *(int2*)(g_rowoff + i0)  = make_int2(ro0, ro1);
        *(uchar2*)(g_cnt + i0)   = make_uchar2((unsigned char)cnt[0], (unsigned char)cnt[1]);
    } else {
        int roa[2] = {ro0, ro1};
        #pragma unroll
        for (int j = 0; j < 2; j++) {
            int i = i0 + j;
            if (i < N) {
                g_hkl0[i] = hk0[j]; g_d0[i] = d0v[j]; g_w0[i] = w0v[j];
                g_rowoff[i] = roa[j]; g_cnt[i] = (unsigned char)cnt[j];
            }
        }
    }
}

// ---- Pass 2: pack; block derives its global base from prior block sums ----
__global__ __launch_bounds__(BLK)
void k_pack(int N) {
    const int b = blockIdx.x;
    const int t = threadIdx.x;
    const int wid = t >> 5, lane = t & 31;

    int partial = 0;
    for (int j = t; j < b; j += BLK) partial += g_blocksum[j];
    #pragma unroll
    for (int o = 16; o > 0; o >>= 1)
        partial += __shfl_down_sync(0xffffffffu, partial, o);
    __shared__ int s_w[8];
    __shared__ int s_base;
    if (lane == 0) s_w[wid] = partial;
    __syncthreads();
    if (t == 0) {
        int s = 0;
        #pragma unroll
        for (int w = 0; w < 8; w++) s += s_w[w];
        s_base = s;
    }
    __syncthreads();

    int i0 = b * ROWS_PB + t * ROWS_PT;
    if (i0 >= N) return;
    if (i0 + ROWS_PT <= N) {
        int2 ro = *(const int2*)(g_rowoff + i0);
        uchar2 c2 = *(const uchar2*)(g_cnt + i0);
        int roa[2] = {ro.x, ro.y};
        int ca[2]  = {c2.x, c2.y};
        #pragma unroll
        for (int j = 0; j < 2; j++) {
            int off = s_base + roa[j];
            int tag = (i0 + j) << 8;
            for (int n = 1; n <= ca[j]; n++)
                g_pack[off + n - 1] = tag | n;
        }
    } else {
        for (int j = 0; j < 2; j++) {
            int i = i0 + j;
            if (i >= N) break;
            int off = s_base + g_rowoff[i];
            int cnt = g_cnt[i];
            int tag = i << 8;
            for (int n = 1; n <= cnt; n++)
                g_pack[off + n - 1] = tag | n;
        }
    }
}

// ---- Pass 3 (fused): meta copy (KB=4) + vectorized scalar outputs (exact R13) ----
template<int LEAD>
__global__ __launch_bounds__(256)
void k_fused(const float* __restrict__ meta, float* __restrict__ out,
             int M, int DMs, unsigned T, unsigned NV, int metaBlocks) {
    if ((int)blockIdx.x >= metaBlocks) {
        int m0 = (blockIdx.x - metaBlocks) * 1024 + threadIdx.x * 4;
        if (m0 + 4 <= M) {
            int4 p4 = *(const int4*)(g_pack + m0);
            int pk[4] = {p4.x, p4.y, p4.z, p4.w};
            float hv[12];
            #pragma unroll
            for (int j = 0; j < 4; j++) {
                int idx = pk[j] >> 8;
                int n   = pk[j] & 255;
                unsigned hp = g_hkl0[idx];
                float fn = (float)n;
                hv[3*j+0] = (float)((int)(hp & 255u) * n);
                hv[3*j+1] = (float)((int)((hp >> 8) & 255u) * n);
                hv[3*j+2] = (float)((int)(hp >> 16) * n);
                out[3 * M + m0 + j] = g_d0[idx] / fn;
                out[4 * M + m0 + j] = g_w0[idx] / fn;
            }
            float4* hdst = (float4*)(out + 3 * (size_t)m0);
            hdst[0] = make_float4(hv[0], hv[1], hv[2],  hv[3]);
            hdst[1] = make_float4(hv[4], hv[5], hv[6],  hv[7]);
            hdst[2] = make_float4(hv[8], hv[9], hv[10], hv[11]);
        } else {
            for (int j = 0; j < 4; j++) {
                int m = m0 + j;
                if (m >= M) break;
                int pack = g_pack[m];
                int idx = pack >> 8;
                int n   = pack & 255;
                unsigned hp = g_hkl0[idx];
                float fn = (float)n;
                out[3 * m + 0] = (float)((int)(hp & 255u) * n);
                out[3 * m + 1] = (float)((int)((hp >> 8) & 255u) * n);
                out[3 * m + 2] = (float)((int)(hp >> 16) * n);
                out[3 * M + m] = g_d0[idx] / fn;
                out[4 * M + m] = g_w0[idx] / fn;
            }
        }
        return;
    }

    const unsigned DMm = (1u << DMs) - 1u;
    const size_t gbase = (size_t)5 * M;
    const unsigned GMAX = T >> 2;

    unsigned w    = blockIdx.x * 8u + (threadIdx.x >> 5);
    int      lane = threadIdx.x & 31;
    unsigned fb   = w * 128u + (unsigned)lane;

    float4 v[5];
    #pragma unroll
    for (int k2 = 0; k2 < 4; k2++) {
        unsigned g = fb + 32u * (unsigned)k2;
        v[k2] = make_float4(0.f, 0.f, 0.f, 0.f);
        if (g < GMAX) {
            unsigned p = 4u * g;
            unsigned idx = ((unsigned)__ldg(&g_pack[p >> DMs])) >> 8;
            v[k2] = *(const float4*)(meta + (size_t)((idx << DMs) + (p & DMm)));
        }
    }
    if (LEAD != 0) {
        v[4] = make_float4(0.f, 0.f, 0.f, 0.f);
        if (lane == 0) {
            unsigned g = w * 128u + 128u;
            if (g < GMAX) {
                unsigned p = 4u * g;
                unsigned idx = ((unsigned)__ldg(&g_pack[p >> DMs])) >> 8;
                v[4] = *(const float4*)(meta + (size_t)((idx << DMs) + (p & DMm)));
            }
        }
    }

    float* dstf = out + gbase + (size_t)LEAD;
    #pragma unroll
    for (int k2 = 0; k2 < 4; k2++) {
        float4 o;
        if (LEAD == 0) {
            o = v[k2];
        } else {
            float4 vnext = (k2 < 3) ? v[k2 + 1] : v[4];
            float nx = __shfl_sync(0xffffffffu, vnext.x, 0);
            float sx = __shfl_down_sync(0xffffffffu, v[k2].x, 1);
            float vnx = (lane == 31) ? nx : sx;
            float vny = 0.f, vnz = 0.f;
            if (LEAD >= 2) {
                float ny = __shfl_sync(0xffffffffu, vnext.y, 0);
                float sy = __shfl_down_sync(0xffffffffu, v[k2].y, 1);
                vny = (lane == 31) ? ny : sy;
            }
            if (LEAD == 3) {
                float nz = __shfl_sync(0xffffffffu, vnext.z, 0);
                float sz = __shfl_down_sync(0xffffffffu, v[k2].z, 1);
                vnz = (lane == 31) ? nz : sz;
            }
            if (LEAD == 1)      o = make_float4(v[k2].y, v[k2].z, v[k2].w, vnx);
            else if (LEAD == 2) o = make_float4(v[k2].z, v[k2].w, vnx, vny);
            else                o = make_float4(v[k2].w, vnx, vny, vnz);
        }
        unsigned f = fb + 32u * (unsigned)k2;
        if (f < NV)
            *(float4*)(dstf + 4 * (size_t)f) = o;
    }

    if (blockIdx.x == 0 && threadIdx.x < 32) {
        if (lane < LEAD) {
            unsigned idx = ((unsigned)g_pack[0]) >> 8;
            out[gbase + lane] = meta[(size_t)((idx << DMs) + lane)];
        }
        unsigned done = (unsigned)LEAD + 4u * NV;
        unsigned tail = T - done;
        if (lane >= 4 && lane < 4 + (int)tail) {
            unsigned p = done + (unsigned)(lane - 4);
            unsigned idx = ((unsigned)g_pack[p >> DMs]) >> 8;
            out[gbase + p] = meta[(size_t)((idx << DMs) + (p & DMm))];
        }
    }
}

// ---- Fallbacks (DM not power of two) ----
__global__ __launch_bounds__(256)
void k_scalar_fb(float* __restrict__ out, int M) {
    int m = blockIdx.x * 256 + threadIdx.x;
    if (m >= M) return;
    int pack = g_pack[m];
    int idx = pack >> 8;
    int n   = pack & 255;
    unsigned hp = g_hkl0[idx];
    float fn = (float)n;
    out[3 * m + 0] = (float)((int)(hp & 255u) * n);
    out[3 * m + 1] = (float)((int)((hp >> 8) & 255u) * n);
    out[3 * m + 2] = (float)((int)(hp >> 16) * n);
    out[3 * M + m] = g_d0[idx] / fn;
    out[4 * M + m] = g_w0[idx] / fn;
}

__global__ __launch_bounds__(256)
void k_meta_fb(const float* __restrict__ meta, float* __restrict__ out, int M, int DM) {
    int gw   = (blockIdx.x * 256 + threadIdx.x) >> 5;
    int lane = threadIdx.x & 31;
    int r = lane >> 3;
    int c = lane & 7;
    int m = gw * 4 + r;
    if (m >= M) return;
    int idx = g_pack[m] >> 8;
    const float* src = meta + (size_t)idx * DM;
    float*       dst = out + (size_t)5 * M + (size_t)m * DM;
    for (int e = c; e < DM; e += 8)
        dst[e] = src[e];
}

extern "C" void kernel_launch(void* const* d_in, const int* in_sizes, int n_in,
                              void* d_out, int out_size) {
    const int*   hkl  = (const int*)  d_in[0];
    const float* dHKL = (const float*)d_in[1];
    const float* wav  = (const float*)d_in[2];
    const float* meta = (const float*)d_in[3];
    const float* dmin = (const float*)d_in[4];

    int N  = in_sizes[1];
    int DM = in_sizes[3] / N;
    int M  = out_size / (5 + DM);

    int B = (N + ROWS_PB - 1) / ROWS_PB;

    k_count<<<B, BLK>>>(hkl, dHKL, wav, dmin, N);
    k_pack<<<B, BLK>>>(N);

    bool pow2 = (DM >= 4) && ((DM & (DM - 1)) == 0);
    if (pow2) {
        int DMs = 0; while ((1 << DMs) < DM) DMs++;
        unsigned T = (unsigned)((size_t)M << DMs);
        int lead = (int)((4u - ((5u * (unsigned)M) & 3u)) & 3u);
        unsigned NV = (T - (unsigned)lead) >> 2;
        unsigned metaWarps = (NV + 127u) / 128u;
        int metaBlocks = (int)((metaWarps + 7u) / 8u);
        int scalarBlocks = (M + 1023) / 1024;
        int grid = metaBlocks + scalarBlocks;
        switch (lead) {
            case 0: k_fused<0><<<grid, 256>>>(meta, (float*)d_out, M, DMs, T, NV, metaBlocks); break;
            case 1: k_fused<1><<<grid, 256>>>(meta, (float*)d_out, M, DMs, T, NV, metaBlocks); break;
            case 2: k_fused<2><<<grid, 256>>>(meta, (float*)d_out, M, DMs, T, NV, metaBlocks); break;
            default: k_fused<3><<<grid, 256>>>(meta, (float*)d_out, M, DMs, T, NV, metaBlocks); break;
        }
    } else {
        k_scalar_fb<<<(M + 255) / 256, 256>>>((float*)d_out, M);
        int rowsPerBlock = 8 * 4;
        k_meta_fb<<<(M + rowsPerBlock - 1) / rowsPerBlock, 256>>>(meta, (float*)d_out, M, DM);
    }
}

// round 16
// speedup vs baseline: 1.1027x; 1.0223x over previous
#include <cuda_runtime.h>
#include <cuda_bf16.h>
#include <cstdint>

// ExpandHarmonics. Output (float32): [hkl 3M | dHKL M | wav M | meta DM*M].
// R16: drop g_rowoff (k_pack recomputes the in-block scan from counts);
//      otherwise exactly R15 (2 rows/thread count/pack, KB=4 fused copy).

#define MAXN   (1 << 20)
#define BLK    256
#define ROWS_PT 2
#define ROWS_PB (BLK * ROWS_PT)                  // 512 rows per block
#define MAXB   ((MAXN + ROWS_PB - 1) / ROWS_PB)
#define MAXM   (1 << 23)

__device__ unsigned char g_cnt[MAXN];
__device__ int           g_blocksum[MAXB];
__device__ int           g_pack[MAXM];       // (src_idx << 8) | harmonic_n
__device__ unsigned int  g_hkl0[MAXN];       // h0 | k0<<8 | l0<<16
__device__ float         g_d0[MAXN];         // dHKL * g
__device__ float         g_w0[MAXN];         // wavelength * g

__device__ __forceinline__ int bgcd(int a, int b) {
    int s = __ffs(a | b) - 1;
    a >>= (__ffs(a) - 1);
    do {
        b >>= (__ffs(b) - 1);
        if (a > b) { int t = a; a = b; b = t; }
        b -= a;
    } while (b);
    return a << s;
}

// ---- Pass 1: count + precompute, 2 rows/thread ----
__global__ __launch_bounds__(BLK)
void k_count(const int* __restrict__ hkl, const float* __restrict__ dHKL,
             const float* __restrict__ wav, const float* __restrict__ dmin, int N) {
    const int t = threadIdx.x;
    const int wid = t >> 5, lane = t & 31;
    const int i0 = blockIdx.x * ROWS_PB + t * ROWS_PT;
    const float dm = __ldg(dmin);

    int hh[2], kk[2], ll[2];
    float dv[2], wv[2];
    bool full = (i0 + ROWS_PT <= N);
    if (full) {
        const int2* hp = (const int2*)(hkl + 3 * i0);    // 3*i0 even -> 8B aligned
        int2 a = hp[0], b = hp[1], c = hp[2];
        hh[0]=a.x; kk[0]=a.y; ll[0]=b.x;
        hh[1]=b.y; kk[1]=c.x; ll[1]=c.y;
        float2 d2 = *(const float2*)(dHKL + i0);
        float2 w2 = *(const float2*)(wav + i0);
        dv[0]=d2.x; dv[1]=d2.y;
        wv[0]=w2.x; wv[1]=w2.y;
    } else {
        #pragma unroll
        for (int j = 0; j < 2; j++) {
            int i = i0 + j;
            if (i < N) {
                hh[j]=hkl[3*i]; kk[j]=hkl[3*i+1]; ll[j]=hkl[3*i+2];
                dv[j]=dHKL[i]; wv[j]=wav[i];
            } else { hh[j]=1; kk[j]=1; ll[j]=1; dv[j]=0.f; wv[j]=0.f; }
        }
    }

    int cnt[2];
    unsigned hk0[2];
    float d0v[2], w0v[2];
    #pragma unroll
    for (int j = 0; j < 2; j++) {
        int g = bgcd(bgcd(hh[j], kk[j]), ll[j]);
        float fg = (float)g;
        float rg = 1.0f / fg;
        float d0 = dv[j] * fg;
        int c = (int)floorf(d0 / dm);
        cnt[j] = (i0 + j < N) ? c : 0;
        unsigned h0 = (unsigned)__float2int_rn((float)hh[j] * rg);
        unsigned k0 = (unsigned)__float2int_rn((float)kk[j] * rg);
        unsigned l0 = (unsigned)__float2int_rn((float)ll[j] * rg);
        hk0[j] = h0 | (k0 << 8) | (l0 << 16);
        d0v[j] = d0;
        w0v[j] = wv[j] * fg;
    }
    int tsum = cnt[0] + cnt[1];

    // warp + block reduction for the block total only (no per-row offsets stored)
    int incl = tsum;
    #pragma unroll
    for (int o = 1; o < 32; o <<= 1) {
        int v = __shfl_up_sync(0xffffffffu, incl, o);
        if (lane >= o) incl += v;
    }
    __shared__ int s_wsum[8];
    if (lane == 31) s_wsum[wid] = incl;
    __syncthreads();
    if (wid == 0 && lane == 0) {
        int s = 0;
        #pragma unroll
        for (int w = 0; w < 8; w++) s += s_wsum[w];
        g_blocksum[blockIdx.x] = s;
    }

    if (full) {
        *(uint2*)(g_hkl0 + i0)   = make_uint2(hk0[0], hk0[1]);
        *(float2*)(g_d0 + i0)    = make_float2(d0v[0], d0v[1]);
        *(float2*)(g_w0 + i0)    = make_float2(w0v[0], w0v[1]);
        *(uchar2*)(g_cnt + i0)   = make_uchar2((unsigned char)cnt[0], (unsigned char)cnt[1]);
    } else {
        #pragma unroll
        for (int j = 0; j < 2; j++) {
            int i = i0 + j;
            if (i < N) {
                g_hkl0[i] = hk0[j]; g_d0[i] = d0v[j]; g_w0[i] = w0v[j];
                g_cnt[i] = (unsigned char)cnt[j];
            }
        }
    }
}

// ---- Pass 2: pack; recomputes the in-block scan from counts ----
__global__ __launch_bounds__(BLK)
void k_pack(int N) {
    const int b = blockIdx.x;
    const int t = threadIdx.x;
    const int wid = t >> 5, lane = t & 31;

    // global base: sum of prior block totals
    int partial = 0;
    for (int j = t; j < b; j += BLK) partial += g_blocksum[j];
    #pragma unroll
    for (int o = 16; o > 0; o >>= 1)
        partial += __shfl_down_sync(0xffffffffu, partial, o);
    __shared__ int s_red[8];
    __shared__ int s_base;
    if (lane == 0) s_red[wid] = partial;
    __syncthreads();
    if (t == 0) {
        int s = 0;
        #pragma unroll
        for (int w = 0; w < 8; w++) s += s_red[w];
        s_base = s;
    }

    // per-row counts
    int i0 = b * ROWS_PB + t * ROWS_PT;
    int cnt[2] = {0, 0};
    if (i0 + ROWS_PT <= N) {
        uchar2 c2 = *(const uchar2*)(g_cnt + i0);
        cnt[0] = c2.x; cnt[1] = c2.y;
    } else {
        for (int j = 0; j < 2; j++) {
            int i = i0 + j;
            if (i < N) cnt[j] = g_cnt[i];
        }
    }
    int tsum = cnt[0] + cnt[1];

    // in-block exclusive scan (recomputed; identical to k_count's structure)
    int incl = tsum;
    #pragma unroll
    for (int o = 1; o < 32; o <<= 1) {
        int v = __shfl_up_sync(0xffffffffu, incl, o);
        if (lane >= o) incl += v;
    }
    __shared__ int s_wbase[8];
    if (lane == 31) s_wbase[wid] = incl;
    __syncthreads();
    if (wid == 0) {
        int v = (lane < 8) ? s_wbase[lane] : 0;
        int sc = v;
        #pragma unroll
        for (int o = 1; o < 8; o <<= 1) {
            int u = __shfl_up_sync(0xffffffffu, sc, o);
            if (lane >= o) sc += u;
        }
        if (lane < 8) s_wbase[lane] = sc - v;
    }
    __syncthreads();

    if (i0 >= N) return;
    int off = s_base + s_wbase[wid] + (incl - tsum);
    #pragma unroll
    for (int j = 0; j < 2; j++) {
        int i = i0 + j;
        if (i >= N) break;
        int tag = i << 8;
        for (int n = 1; n <= cnt[j]; n++)
            g_pack[off + n - 1] = tag | n;
        off += cnt[j];
    }
}

// ---- Pass 3 (fused): meta copy (KB=4) + vectorized scalar outputs (exact R13/R15) ----
template<int LEAD>
__global__ __launch_bounds__(256)
void k_fused(const float* __restrict__ meta, float* __restrict__ out,
             int M, int DMs, unsigned T, unsigned NV, int metaBlocks) {
    if ((int)blockIdx.x >= metaBlocks) {
        int m0 = (blockIdx.x - metaBlocks) * 1024 + threadIdx.x * 4;
        if (m0 + 4 <= M) {
            int4 p4 = *(const int4*)(g_pack + m0);
            int pk[4] = {p4.x, p4.y, p4.z, p4.w};
            float hv[12];
            #pragma unroll
            for (int j = 0; j < 4; j++) {
                int idx = pk[j] >> 8;
                int n   = pk[j] & 255;
                unsigned hp = g_hkl0[idx];
                float fn = (float)n;
                hv[3*j+0] = (float)((int)(hp & 255u) * n);
                hv[3*j+1] = (float)((int)((hp >> 8) & 255u) * n);
                hv[3*j+2] = (float)((int)(hp >> 16) * n);
                out[3 * M + m0 + j] = g_d0[idx] / fn;
                out[4 * M + m0 + j] = g_w0[idx] / fn;
            }
            float4* hdst = (float4*)(out + 3 * (size_t)m0);
            hdst[0] = make_float4(hv[0], hv[1], hv[2],  hv[3]);
            hdst[1] = make_float4(hv[4], hv[5], hv[6],  hv[7]);
            hdst[2] = make_float4(hv[8], hv[9], hv[10], hv[11]);
        } else {
            for (int j = 0; j < 4; j++) {
                int m = m0 + j;
                if (m >= M) break;
                int pack = g_pack[m];
                int idx = pack >> 8;
                int n   = pack & 255;
                unsigned hp = g_hkl0[idx];
                float fn = (float)n;
                out[3 * m + 0] = (float)((int)(hp & 255u) * n);
                out[3 * m + 1] = (float)((int)((hp >> 8) & 255u) * n);
                out[3 * m + 2] = (float)((int)(hp >> 16) * n);
                out[3 * M + m] = g_d0[idx] / fn;
                out[4 * M + m] = g_w0[idx] / fn;
            }
        }
        return;
    }

    const unsigned DMm = (1u << DMs) - 1u;
    const size_t gbase = (size_t)5 * M;
    const unsigned GMAX = T >> 2;

    unsigned w    = blockIdx.x * 8u + (threadIdx.x >> 5);
    int      lane = threadIdx.x & 31;
    unsigned fb   = w * 128u + (unsigned)lane;

    float4 v[5];
    #pragma unroll
    for (int k2 = 0; k2 < 4; k2++) {
        unsigned g = fb + 32u * (unsigned)k2;
        v[k2] = make_float4(0.f, 0.f, 0.f, 0.f);
        if (g < GMAX) {
            unsigned p = 4u * g;
            unsigned idx = ((unsigned)__ldg(&g_pack[p >> DMs])) >> 8;
            v[k2] = *(const float4*)(meta + (size_t)((idx << DMs) + (p & DMm)));
        }
    }
    if (LEAD != 0) {
        v[4] = make_float4(0.f, 0.f, 0.f, 0.f);
        if (lane == 0) {
            unsigned g = w * 128u + 128u;
            if (g < GMAX) {
                unsigned p = 4u * g;
                unsigned idx = ((unsigned)__ldg(&g_pack[p >> DMs])) >> 8;
                v[4] = *(const float4*)(meta + (size_t)((idx << DMs) + (p & DMm)));
            }
        }
    }

    float* dstf = out + gbase + (size_t)LEAD;
    #pragma unroll
    for (int k2 = 0; k2 < 4; k2++) {
        float4 o;
        if (LEAD == 0) {
            o = v[k2];
        } else {
            float4 vnext = (k2 < 3) ? v[k2 + 1] : v[4];
            float nx = __shfl_sync(0xffffffffu, vnext.x, 0);
            float sx = __shfl_down_sync(0xffffffffu, v[k2].x, 1);
            float vnx = (lane == 31) ? nx : sx;
            float vny = 0.f, vnz = 0.f;
            if (LEAD >= 2) {
                float ny = __shfl_sync(0xffffffffu, vnext.y, 0);
                float sy = __shfl_down_sync(0xffffffffu, v[k2].y, 1);
                vny = (lane == 31) ? ny : sy;
            }
            if (LEAD == 3) {
                float nz = __shfl_sync(0xffffffffu, vnext.z, 0);
                float sz = __shfl_down_sync(0xffffffffu, v[k2].z, 1);
                vnz = (lane == 31) ? nz : sz;
            }
            if (LEAD == 1)      o = make_float4(v[k2].y, v[k2].z, v[k2].w, vnx);
            else if (LEAD == 2) o = make_float4(v[k2].z, v[k2].w, vnx, vny);
            else                o = make_float4(v[k2].w, vnx, vny, vnz);
        }
        unsigned f = fb + 32u * (unsigned)k2;
        if (f < NV)
            *(float4*)(dstf + 4 * (size_t)f) = o;
    }

    if (blockIdx.x == 0 && threadIdx.x < 32) {
        if (lane < LEAD) {
            unsigned idx = ((unsigned)g_pack[0]) >> 8;
            out[gbase + lane] = meta[(size_t)((idx << DMs) + lane)];
        }
        unsigned done = (unsigned)LEAD + 4u * NV;
        unsigned tail = T - done;
        if (lane >= 4 && lane < 4 + (int)tail) {
            unsigned p = done + (unsigned)(lane - 4);
            unsigned idx = ((unsigned)g_pack[p >> DMs]) >> 8;
            out[gbase + p] = meta[(size_t)((idx << DMs) + (p & DMm))];
        }
    }
}

// ---- Fallbacks (DM not power of two) ----
__global__ __launch_bounds__(256)
void k_scalar_fb(float* __restrict__ out, int M) {
    int m = blockIdx.x * 256 + threadIdx.x;
    if (m >= M) return;
    int pack = g_pack[m];
    int idx = pack >> 8;
    int n   = pack & 255;
    unsigned hp = g_hkl0[idx];
    float fn = (float)n;
    out[3 * m + 0] = (float)((int)(hp & 255u) * n);
    out[3 * m + 1] = (float)((int)((hp >> 8) & 255u) * n);
    out[3 * m + 2] = (float)((int)(hp >> 16) * n);
    out[3 * M + m] = g_d0[idx] / fn;
    out[4 * M + m] = g_w0[idx] / fn;
}

__global__ __launch_bounds__(256)
void k_meta_fb(const float* __restrict__ meta, float* __restrict__ out, int M, int DM) {
    int gw   = (blockIdx.x * 256 + threadIdx.x) >> 5;
    int lane = threadIdx.x & 31;
    int r = lane >> 3;
    int c = lane & 7;
    int m = gw * 4 + r;
    if (m >= M) return;
    int idx = g_pack[m] >> 8;
    const float* src = meta + (size_t)idx * DM;
    float*       dst = out + (size_t)5 * M + (size_t)m * DM;
    for (int e = c; e < DM; e += 8)
        dst[e] = src[e];
}

extern "C" void kernel_launch(void* const* d_in, const int* in_sizes, int n_in,
                              void* d_out, int out_size) {
    const int*   hkl  = (const int*)  d_in[0];
    const float* dHKL = (const float*)d_in[1];
    const float* wav  = (const float*)d_in[2];
    const float* meta = (const float*)d_in[3];
    const float* dmin = (const float*)d_in[4];

    int N  = in_sizes[1];
    int DM = in_sizes[3] / N;
    int M  = out_size / (5 + DM);

    int B = (N + ROWS_PB - 1) / ROWS_PB;

    k_count<<<B, BLK>>>(hkl, dHKL, wav, dmin, N);
    k_pack<<<B, BLK>>>(N);

    bool pow2 = (DM >= 4) && ((DM & (DM - 1)) == 0);
    if (pow2) {
        int DMs = 0; while ((1 << DMs) < DM) DMs++;
        unsigned T = (unsigned)((size_t)M << DMs);
        int lead = (int)((4u - ((5u * (unsigned)M) & 3u)) & 3u);
        unsigned NV = (T - (unsigned)lead) >> 2;
        unsigned metaWarps = (NV + 127u) / 128u;
        int metaBlocks = (int)((metaWarps + 7u) / 8u);
        int scalarBlocks = (M + 1023) / 1024;
        int grid = metaBlocks + scalarBlocks;
        switch (lead) {
            case 0: k_fused<0><<<grid, 256>>>(meta, (float*)d_out, M, DMs, T, NV, metaBlocks); break;
            case 1: k_fused<1><<<grid, 256>>>(meta, (float*)d_out, M, DMs, T, NV, metaBlocks); break;
            case 2: k_fused<2><<<grid, 256>>>(meta, (float*)d_out, M, DMs, T, NV, metaBlocks); break;
            default: k_fused<3><<<grid, 256>>>(meta, (float*)d_out, M, DMs, T, NV, metaBlocks); break;
        }
    } else {
        k_scalar_fb<<<(M + 255) / 256, 256>>>((float*)d_out, M);
        int rowsPerBlock = 8 * 4;
        k_meta_fb<<<(M + rowsPerBlock - 1) / rowsPerBlock, 256>>>(meta, (float*)d_out, M, DM);
    }
}